// round 1
// baseline (speedup 1.0000x reference)
#include <cuda_runtime.h>
#include <cuda_bf16.h>
#include <cstdint>

// SpatiallyJitterColorChannels: per-(b,c) 2D roll of x[64,3,512,512] fp32.
// out[b,c,h,w] = x[b,c,(h - sh) & 511, (w - sw) & 511],  sh/sw = shifts[b,c,:] - 2.
//
// Memory-bound copy: 402 MB total traffic. Strategy:
//   - one float4 output store per thread (perfectly coalesced STG.128)
//   - 4 scalar input loads (W-shift of +/-2 elems breaks 16B alignment;
//     warp reads remain contiguous +/- 8 bytes -> ~1 extra sector/warp)
//   - power-of-two dims: mod -> & 511, all index math is shift/AND.

#define H 512
#define W 512
#define HW (H * W)            // 262144 floats per plane
#define F4_PER_PLANE (HW / 4) // 65536
#define SHIFT 2

__global__ void __launch_bounds__(256) roll2d_kernel(
    const float* __restrict__ x,
    const int*   __restrict__ shifts,   // [B, C, 2] int32 in [0, 2*SHIFT]
    float*       __restrict__ out)
{
    int idx = blockIdx.x * blockDim.x + threadIdx.x;   // float4 index
    int plane  = idx >> 16;            // / F4_PER_PLANE  (b*3 + c)
    int within = idx & (F4_PER_PLANE - 1);
    int h  = within >> 7;              // 128 float4 per row
    int w0 = (within & 127) << 2;      // starting w of this float4

    int sh = shifts[plane * 2 + 0] - SHIFT;
    int sw = shifts[plane * 2 + 1] - SHIFT;

    int hs = (h - sh) & (H - 1);
    const float* src = x + ((size_t)plane * HW) + ((size_t)hs << 9);

    float4 v;
    v.x = __ldg(&src[(w0 + 0 - sw) & (W - 1)]);
    v.y = __ldg(&src[(w0 + 1 - sw) & (W - 1)]);
    v.z = __ldg(&src[(w0 + 2 - sw) & (W - 1)]);
    v.w = __ldg(&src[(w0 + 3 - sw) & (W - 1)]);

    reinterpret_cast<float4*>(out)[idx] = v;
}

extern "C" void kernel_launch(void* const* d_in, const int* in_sizes, int n_in,
                              void* d_out, int out_size)
{
    const float* x      = (const float*)d_in[0];
    const int*   shifts = (const int*)d_in[1];
    float*       out    = (float*)d_out;

    // out_size = 64*3*512*512 = 50331648 floats = 12582912 float4s
    int n_f4 = out_size / 4;
    int threads = 256;
    int blocks = (n_f4 + threads - 1) / threads;   // 49152
    roll2d_kernel<<<blocks, threads>>>(x, shifts, out);
}

// round 2
// speedup vs baseline: 1.1300x; 1.1300x over previous
#include <cuda_runtime.h>
#include <cuda_bf16.h>
#include <cstdint>

// SpatiallyJitterColorChannels: per-(b,c) 2D roll of x[64,3,512,512] fp32.
// out[b,c,h,w] = x[b,c,(h-sh)&511,(w-sw)&511], sh/sw = shifts[b,c,:]-2, |s|<=2.
//
// R2 strategy: all-aligned traffic.
//  - Since |sw| <= 2, each output float4 lies within two ADJACENT aligned
//    source quads A,B. Load both with LDG.128 (B of thread t == A of thread
//    t+1 -> L1 hit; DRAM read traffic stays exact) and register-select.
//  - Select pattern o = (sw>0 ? 4-sw : -sw) in {0..3} is uniform per plane:
//    non-divergent switch, pure register moves.
//  - ILP=2: each thread produces 2 output float4s (4 LDG.128 in flight).
//    Block of 256 threads covers 512 consecutive float4s = always within one
//    plane (65536 f4/plane % 512 == 0), so shifts are loaded once.

#define SHIFT 2

__global__ void __launch_bounds__(256) roll2d_kernel(
    const float* __restrict__ x,
    const int*   __restrict__ shifts,   // [B, C, 2] int32 in [0, 2*SHIFT]
    float*       __restrict__ out)
{
    int base  = blockIdx.x * 512 + threadIdx.x;   // float4 index of element 0
    int plane = base >> 16;                       // / 65536 f4 per plane

    int sh = shifts[plane * 2 + 0] - SHIFT;
    int sw = shifts[plane * 2 + 1] - SHIFT;

    int qa_off, o;
    if (sw > 0) { qa_off = -4; o = 4 - sw; }      // o in {2,3}
    else        { qa_off = 0;  o = -sw;    }      // o in {0,1,2}

    const float* planep = x + ((size_t)plane << 18);   // * 262144

    float4 A[2], B[2];
    int    oidx[2];

    #pragma unroll
    for (int e = 0; e < 2; e++) {
        int idx    = base + e * 256;
        int within = idx & 65535;
        int h      = within >> 7;            // 128 f4 per row
        int w0     = (within & 127) << 2;    // starting column
        int hs     = (h - sh) & 511;
        const float* rowp = planep + (hs << 9);
        int qa = (w0 + qa_off) & 511;        // aligned quad, never straddles row
        int qb = (qa + 4) & 511;
        A[e] = *reinterpret_cast<const float4*>(rowp + qa);
        B[e] = *reinterpret_cast<const float4*>(rowp + qb);
        oidx[e] = idx;
    }

    #pragma unroll
    for (int e = 0; e < 2; e++) {
        float4 v;
        switch (o) {   // uniform per plane -> no divergence
            case 0:  v = A[e]; break;
            case 1:  v = make_float4(A[e].y, A[e].z, A[e].w, B[e].x); break;
            case 2:  v = make_float4(A[e].z, A[e].w, B[e].x, B[e].y); break;
            default: v = make_float4(A[e].w, B[e].x, B[e].y, B[e].z); break;
        }
        reinterpret_cast<float4*>(out)[oidx[e]] = v;
    }
}

extern "C" void kernel_launch(void* const* d_in, const int* in_sizes, int n_in,
                              void* d_out, int out_size)
{
    const float* x      = (const float*)d_in[0];
    const int*   shifts = (const int*)d_in[1];
    float*       out    = (float*)d_out;

    // out_size = 50331648 floats = 12582912 float4s; 512 f4 per block
    int n_f4   = out_size / 4;
    int blocks = n_f4 / 512;                 // 24576
    roll2d_kernel<<<blocks, 256>>>(x, shifts, out);
}